// round 7
// baseline (speedup 1.0000x reference)
#include <cuda_runtime.h>
#include <cuda_bf16.h>
#include <cstdint>

// Weighted keypoint MSE loss:
//   oob = target outside [0,1024]^2; weight = oob ? 0.01 : 1.0
//   loss = sum_bk( weight * ||output-target||^2 ) / 4096
//
// R7: R5's TMA ring, but the per-iteration __syncthreads is replaced by
// per-stage empty mbarriers (8 warp arrivals). Only thread 0 waits on empty
// before reissuing; other warps run ahead to the next full stage.
// 6-stage ring x 4KB/array, grid = 148*4 (one balanced wave), 256 thr/CTA.

#define HEIGHT_F 1024.0f
#define WIDTH_F  1024.0f
#define OOB_W    0.01f
#define B_DIM    4096.0

#define NBLOCKS     592          // 148 SMs * 4 CTAs
#define NTHREADS    256
#define NSTAGES     6
#define CHUNK_F4    256          // float4 per chunk per array (4KB)
#define CHUNK_BYTES (CHUNK_F4 * 16)
#define SMEM_BYTES  (NSTAGES * 2 * CHUNK_BYTES)   // 48KB

__device__ double g_partials[NBLOCKS];
__device__ unsigned int g_count;   // zero-init; atomicInc self-wraps -> replay-safe

__device__ __forceinline__ uint32_t smem_u32(const void* p) {
    return (uint32_t)__cvta_generic_to_shared(p);
}

__device__ __forceinline__ void mbar_init(uint32_t mbar, uint32_t count) {
    asm volatile("mbarrier.init.shared.b64 [%0], %1;" :: "r"(mbar), "r"(count) : "memory");
}

__device__ __forceinline__ void mbar_arrive(uint32_t mbar) {
    asm volatile("mbarrier.arrive.shared.b64 _, [%0];" :: "r"(mbar) : "memory");
}

__device__ __forceinline__ void mbar_expect_tx(uint32_t mbar, uint32_t bytes) {
    asm volatile("mbarrier.arrive.expect_tx.shared.b64 _, [%0], %1;"
                 :: "r"(mbar), "r"(bytes) : "memory");
}

__device__ __forceinline__ void mbar_wait(uint32_t mbar, uint32_t parity) {
    uint32_t done;
    asm volatile(
        "{\n\t.reg .pred p;\n\t"
        "mbarrier.try_wait.parity.acquire.cta.shared::cta.b64 p, [%1], %2;\n\t"
        "selp.b32 %0, 1, 0, p;\n\t}"
        : "=r"(done) : "r"(mbar), "r"(parity) : "memory");
    if (!done) {
        asm volatile(
            "{\n\t.reg .pred P1;\n\t"
            "WAIT_LOOP_%=:\n\t"
            "mbarrier.try_wait.parity.acquire.cta.shared::cta.b64 P1, [%0], %1, 0x989680;\n\t"
            "@P1 bra.uni WAIT_DONE_%=;\n\t"
            "bra.uni WAIT_LOOP_%=;\n\t"
            "WAIT_DONE_%=:\n\t}"
            :: "r"(mbar), "r"(parity) : "memory");
    }
}

__device__ __forceinline__ void bulk_g2s(uint32_t dst_smem, const void* src_gmem,
                                         uint32_t bytes, uint32_t mbar) {
    asm volatile(
        "cp.async.bulk.shared::cta.global.mbarrier::complete_tx::bytes [%0], [%1], %2, [%3];"
        :: "r"(dst_smem), "l"(src_gmem), "r"(bytes), "r"(mbar) : "memory");
}

__device__ __forceinline__ float pair_loss(float4 o, float4 t) {
    float dx0 = o.x - t.x;
    float dy0 = o.y - t.y;
    float sq0 = fmaf(dx0, dx0, dy0 * dy0);
    bool oob0 = (t.x < 0.0f) | (t.x > WIDTH_F) | (t.y < 0.0f) | (t.y > HEIGHT_F);
    float w0 = oob0 ? OOB_W : 1.0f;

    float dx1 = o.z - t.z;
    float dy1 = o.w - t.w;
    float sq1 = fmaf(dx1, dx1, dy1 * dy1);
    bool oob1 = (t.z < 0.0f) | (t.z > WIDTH_F) | (t.w < 0.0f) | (t.w > HEIGHT_F);
    float w1 = oob1 ? OOB_W : 1.0f;

    return fmaf(w0, sq0, w1 * sq1);
}

__device__ __forceinline__ double block_reduce(double v, double* warp_sums) {
    #pragma unroll
    for (int off = 16; off > 0; off >>= 1)
        v += __shfl_down_sync(0xFFFFFFFFu, v, off);
    int lane = threadIdx.x & 31;
    int wid  = threadIdx.x >> 5;
    if (lane == 0) warp_sums[wid] = v;
    __syncthreads();
    if (wid == 0) {
        v = (lane < (NTHREADS >> 5)) ? warp_sums[lane] : 0.0;
        #pragma unroll
        for (int off = 4; off > 0; off >>= 1)
            v += __shfl_down_sync(0xFFFFFFFFu, v, off);
    }
    return v;  // valid in thread 0
}

__global__ __launch_bounds__(NTHREADS) void loss_kernel(
    const float4* __restrict__ outp,
    const float4* __restrict__ tgt,
    int n4,
    float* __restrict__ out)
{
    extern __shared__ __align__(16) float4 ring[];  // [NSTAGES][2*CHUNK_F4]: o then t

    __shared__ __align__(8) unsigned long long mb_full[NSTAGES];
    __shared__ __align__(8) unsigned long long mb_empty[NSTAGES];
    __shared__ double warp_sums[NTHREADS / 32];
    __shared__ bool is_last;

    const int tid  = threadIdx.x;
    const int lane = tid & 31;
    const int bid  = blockIdx.x;
    const int chunks_total = n4 / CHUNK_F4;

    if (tid == 0) {
        #pragma unroll
        for (int s = 0; s < NSTAGES; s++) {
            mbar_init(smem_u32(&mb_full[s]), 1);     // completed by TMA tx bytes
            mbar_init(smem_u32(&mb_empty[s]), 8);    // 8 consumer-warp arrivals
        }
    }
    __syncthreads();

    // ---- prologue: thread 0 fills the ring ----
    if (tid == 0) {
        #pragma unroll
        for (int p = 0; p < NSTAGES; p++) {
            int c = bid + p * NBLOCKS;
            if (c < chunks_total) {
                uint32_t mbf = smem_u32(&mb_full[p]);
                mbar_expect_tx(mbf, 2 * CHUNK_BYTES);
                float4* s_o = ring + p * (2 * CHUNK_F4);
                bulk_g2s(smem_u32(s_o), outp + (size_t)c * CHUNK_F4, CHUNK_BYTES, mbf);
                bulk_g2s(smem_u32(s_o + CHUNK_F4), tgt + (size_t)c * CHUNK_F4, CHUNK_BYTES, mbf);
            }
        }
    }

    double acc = 0.0;

    // ---- main loop ----
    int stage = 0, phase = 0;
    for (int c = bid; c < chunks_total; c += NBLOCKS) {
        uint32_t mbf = smem_u32(&mb_full[stage]);
        mbar_wait(mbf, phase);

        const float4* s_o = ring + stage * (2 * CHUNK_F4);
        float4 o = s_o[tid];
        float4 t = s_o[tid + CHUNK_F4];
        acc += (double)pair_loss(o, t);

        __syncwarp();
        if (lane == 0) mbar_arrive(smem_u32(&mb_empty[stage]));

        // only thread 0 blocks on the empty barrier, then reissues this stage
        if (tid == 0) {
            int cn = c + NSTAGES * NBLOCKS;
            if (cn < chunks_total) {
                uint32_t mbe = smem_u32(&mb_empty[stage]);
                mbar_wait(mbe, phase);
                mbar_expect_tx(mbf, 2 * CHUNK_BYTES);
                float4* d_o = ring + stage * (2 * CHUNK_F4);
                bulk_g2s(smem_u32(d_o), outp + (size_t)cn * CHUNK_F4, CHUNK_BYTES, mbf);
                bulk_g2s(smem_u32(d_o + CHUNK_F4), tgt + (size_t)cn * CHUNK_F4, CHUNK_BYTES, mbf);
            }
        }

        if (++stage == NSTAGES) { stage = 0; phase ^= 1; }
    }

    // ---- tail (n4 not multiple of CHUNK_F4; empty for this shape) ----
    if (bid == 0) {
        for (int i = chunks_total * CHUNK_F4 + tid; i < n4; i += NTHREADS) {
            float4 o = __ldcs(outp + i);
            float4 t = __ldcs(tgt + i);
            acc += (double)pair_loss(o, t);
        }
    }

    // ---- reduce + last-block finalize ----
    double bsum = block_reduce(acc, warp_sums);

    if (tid == 0) {
        g_partials[bid] = bsum;
        __threadfence();
        unsigned int old = atomicInc(&g_count, NBLOCKS - 1);  // wraps to 0
        is_last = (old == NBLOCKS - 1);
    }
    __syncthreads();

    if (is_last) {
        __threadfence();
        double v = 0.0;
        for (int j = tid; j < NBLOCKS; j += NTHREADS)
            v += g_partials[j];
        __syncthreads();
        double total = block_reduce(v, warp_sums);
        if (tid == 0)
            out[0] = (float)(total / B_DIM);
    }
}

extern "C" void kernel_launch(void* const* d_in, const int* in_sizes, int n_in,
                              void* d_out, int out_size) {
    const float4* outp = (const float4*)d_in[0];
    const float4* tgt  = (const float4*)d_in[1];
    int n4 = in_sizes[0] / 4;   // float4 count (2 keypoints each)

    cudaFuncSetAttribute(loss_kernel,
                         cudaFuncAttributeMaxDynamicSharedMemorySize, SMEM_BYTES);

    loss_kernel<<<NBLOCKS, NTHREADS, SMEM_BYTES>>>(outp, tgt, n4, (float*)d_out);
}

// round 8
// speedup vs baseline: 1.2199x; 1.2199x over previous
#include <cuda_runtime.h>
#include <cuda_bf16.h>
#include <cstdint>

// Weighted keypoint MSE loss:
//   oob = target outside [0,1024]^2; weight = oob ? 0.01 : 1.0
//   loss = sum_bk( weight * ||output-target||^2 ) / 4096
//
// R8 = R5 (best: TMA ring + per-stage __syncthreads) with 2x chunks:
// 3-stage ring, 8KB per array per stage (48KB smem, 4 CTAs/SM), so the
// per-iteration sync cost is paid half as often. grid = 148*4 = one wave.

#define HEIGHT_F 1024.0f
#define WIDTH_F  1024.0f
#define OOB_W    0.01f
#define B_DIM    4096.0

#define NBLOCKS     592          // 148 SMs * 4 CTAs
#define NTHREADS    256
#define NSTAGES     3
#define CHUNK_F4    512          // float4 per chunk per array (8KB)
#define CHUNK_BYTES (CHUNK_F4 * 16)
#define SMEM_BYTES  (NSTAGES * 2 * CHUNK_BYTES)   // 48KB

__device__ double g_partials[NBLOCKS];
__device__ unsigned int g_count;   // zero-init; atomicInc self-wraps -> replay-safe

__device__ __forceinline__ uint32_t smem_u32(const void* p) {
    return (uint32_t)__cvta_generic_to_shared(p);
}

__device__ __forceinline__ void mbar_init(uint32_t mbar, uint32_t count) {
    asm volatile("mbarrier.init.shared.b64 [%0], %1;" :: "r"(mbar), "r"(count) : "memory");
}

__device__ __forceinline__ void mbar_expect_tx(uint32_t mbar, uint32_t bytes) {
    asm volatile("mbarrier.arrive.expect_tx.shared.b64 _, [%0], %1;"
                 :: "r"(mbar), "r"(bytes) : "memory");
}

__device__ __forceinline__ void mbar_wait(uint32_t mbar, uint32_t parity) {
    uint32_t done;
    asm volatile(
        "{\n\t.reg .pred p;\n\t"
        "mbarrier.try_wait.parity.acquire.cta.shared::cta.b64 p, [%1], %2;\n\t"
        "selp.b32 %0, 1, 0, p;\n\t}"
        : "=r"(done) : "r"(mbar), "r"(parity) : "memory");
    if (!done) {
        asm volatile(
            "{\n\t.reg .pred P1;\n\t"
            "WAIT_LOOP_%=:\n\t"
            "mbarrier.try_wait.parity.acquire.cta.shared::cta.b64 P1, [%0], %1, 0x989680;\n\t"
            "@P1 bra.uni WAIT_DONE_%=;\n\t"
            "bra.uni WAIT_LOOP_%=;\n\t"
            "WAIT_DONE_%=:\n\t}"
            :: "r"(mbar), "r"(parity) : "memory");
    }
}

__device__ __forceinline__ void bulk_g2s(uint32_t dst_smem, const void* src_gmem,
                                         uint32_t bytes, uint32_t mbar) {
    asm volatile(
        "cp.async.bulk.shared::cta.global.mbarrier::complete_tx::bytes [%0], [%1], %2, [%3];"
        :: "r"(dst_smem), "l"(src_gmem), "r"(bytes), "r"(mbar) : "memory");
}

__device__ __forceinline__ float pair_loss(float4 o, float4 t) {
    float dx0 = o.x - t.x;
    float dy0 = o.y - t.y;
    float sq0 = fmaf(dx0, dx0, dy0 * dy0);
    bool oob0 = (t.x < 0.0f) | (t.x > WIDTH_F) | (t.y < 0.0f) | (t.y > HEIGHT_F);
    float w0 = oob0 ? OOB_W : 1.0f;

    float dx1 = o.z - t.z;
    float dy1 = o.w - t.w;
    float sq1 = fmaf(dx1, dx1, dy1 * dy1);
    bool oob1 = (t.z < 0.0f) | (t.z > WIDTH_F) | (t.w < 0.0f) | (t.w > HEIGHT_F);
    float w1 = oob1 ? OOB_W : 1.0f;

    return fmaf(w0, sq0, w1 * sq1);
}

__device__ __forceinline__ double block_reduce(double v, double* warp_sums) {
    #pragma unroll
    for (int off = 16; off > 0; off >>= 1)
        v += __shfl_down_sync(0xFFFFFFFFu, v, off);
    int lane = threadIdx.x & 31;
    int wid  = threadIdx.x >> 5;
    if (lane == 0) warp_sums[wid] = v;
    __syncthreads();
    if (wid == 0) {
        v = (lane < (NTHREADS >> 5)) ? warp_sums[lane] : 0.0;
        #pragma unroll
        for (int off = 4; off > 0; off >>= 1)
            v += __shfl_down_sync(0xFFFFFFFFu, v, off);
    }
    return v;  // valid in thread 0
}

__global__ __launch_bounds__(NTHREADS) void loss_kernel(
    const float4* __restrict__ outp,
    const float4* __restrict__ tgt,
    int n4,
    float* __restrict__ out)
{
    extern __shared__ __align__(16) float4 ring[];  // [NSTAGES][2*CHUNK_F4]: o then t

    __shared__ __align__(8) unsigned long long s_mbar[NSTAGES];
    __shared__ double warp_sums[NTHREADS / 32];
    __shared__ bool is_last;

    const int tid = threadIdx.x;
    const int bid = blockIdx.x;
    const int chunks_total = n4 / CHUNK_F4;

    if (tid == 0) {
        #pragma unroll
        for (int s = 0; s < NSTAGES; s++)
            mbar_init(smem_u32(&s_mbar[s]), 1);
    }
    __syncthreads();

    // ---- prologue: fill the ring ----
    if (tid == 0) {
        #pragma unroll
        for (int p = 0; p < NSTAGES; p++) {
            int c = bid + p * NBLOCKS;
            if (c < chunks_total) {
                uint32_t mb = smem_u32(&s_mbar[p]);
                mbar_expect_tx(mb, 2 * CHUNK_BYTES);
                float4* s_o = ring + p * (2 * CHUNK_F4);
                bulk_g2s(smem_u32(s_o), outp + (size_t)c * CHUNK_F4, CHUNK_BYTES, mb);
                bulk_g2s(smem_u32(s_o + CHUNK_F4), tgt + (size_t)c * CHUNK_F4, CHUNK_BYTES, mb);
            }
        }
    }

    double acc = 0.0;

    // ---- main pipeline ----
    int stage = 0, phase = 0;
    for (int c = bid; c < chunks_total; c += NBLOCKS) {
        uint32_t mb = smem_u32(&s_mbar[stage]);
        mbar_wait(mb, phase);

        const float4* s_o = ring + stage * (2 * CHUNK_F4);
        const float4* s_t = s_o + CHUNK_F4;
        float4 o0 = s_o[tid];
        float4 t0 = s_t[tid];
        float4 o1 = s_o[tid + NTHREADS];
        float4 t1 = s_t[tid + NTHREADS];
        acc += (double)(pair_loss(o0, t0) + pair_loss(o1, t1));

        __syncthreads();   // everyone done reading stage

        if (tid == 0) {
            int cn = c + NSTAGES * NBLOCKS;
            if (cn < chunks_total) {
                mbar_expect_tx(mb, 2 * CHUNK_BYTES);
                float4* d_o = ring + stage * (2 * CHUNK_F4);
                bulk_g2s(smem_u32(d_o), outp + (size_t)cn * CHUNK_F4, CHUNK_BYTES, mb);
                bulk_g2s(smem_u32(d_o + CHUNK_F4), tgt + (size_t)cn * CHUNK_F4, CHUNK_BYTES, mb);
            }
        }

        if (++stage == NSTAGES) { stage = 0; phase ^= 1; }
    }

    // ---- tail (n4 not multiple of CHUNK_F4; empty for this shape) ----
    if (bid == 0) {
        for (int i = chunks_total * CHUNK_F4 + tid; i < n4; i += NTHREADS) {
            float4 o = __ldcs(outp + i);
            float4 t = __ldcs(tgt + i);
            acc += (double)pair_loss(o, t);
        }
    }

    // ---- reduce + last-block finalize ----
    double bsum = block_reduce(acc, warp_sums);

    if (tid == 0) {
        g_partials[bid] = bsum;
        __threadfence();
        unsigned int old = atomicInc(&g_count, NBLOCKS - 1);  // wraps to 0
        is_last = (old == NBLOCKS - 1);
    }
    __syncthreads();

    if (is_last) {
        __threadfence();
        double v = 0.0;
        for (int j = tid; j < NBLOCKS; j += NTHREADS)
            v += g_partials[j];
        __syncthreads();
        double total = block_reduce(v, warp_sums);
        if (tid == 0)
            out[0] = (float)(total / B_DIM);
    }
}

extern "C" void kernel_launch(void* const* d_in, const int* in_sizes, int n_in,
                              void* d_out, int out_size) {
    const float4* outp = (const float4*)d_in[0];
    const float4* tgt  = (const float4*)d_in[1];
    int n4 = in_sizes[0] / 4;   // float4 count (2 keypoints each)

    cudaFuncSetAttribute(loss_kernel,
                         cudaFuncAttributeMaxDynamicSharedMemorySize, SMEM_BYTES);

    loss_kernel<<<NBLOCKS, NTHREADS, SMEM_BYTES>>>(outp, tgt, n4, (float*)d_out);
}